// round 15
// baseline (speedup 1.0000x reference)
#include <cuda_runtime.h>
#include <cstdint>

// ---------------- problem constants ----------------
constexpr int F = 64;
constexpr int H = 128;
constexpr int O = 512;
constexpr int K = F * H;            // 8192
constexpr int MT = 128;             // CTA M tile
constexpr int NT = 128;             // CTA N tile
constexpr int KB = 16;              // K per pipeline stage
constexpr int NSTAGES = K / KB;     // 512
constexpr int THREADS = 256;        // 8 warps: 4 (m) x 2 (n), warp tile 32x64

// ---------------- smem layout (float offsets) ----------------
// A stored FRAGMENT-PERMUTED: [buf][bk(2)][bm(8)][lane(32)][slot(4)]
//   value A(rr within m16, kq within k8) -> lane=(rr&7)*4+(kq&3), slot=(rr>>3)+2*(kq>>2)
// so a consumer thread's whole m16n8k8 A fragment is ONE aligned LDS.128.
constexpr int BSUM      = 0;                          // 128 floats
constexpr int AS        = 128;                        // 2 bufs x 2048 floats
constexpr int AS_SZ     = 2048;                       // 2*8*32*4
constexpr int BBS       = AS + 2 * AS_SZ;             // 4224
constexpr int BS_STRIDE = 136;                        // 128 + 8 pad (conflict-free)
constexpr int BS_SZ     = KB * BS_STRIDE;             // 2176
constexpr int SMEM_FLOATS = BBS + 2 * BS_SZ;          // 8576
constexpr int SMEM_BYTES  = SMEM_FLOATS * 4;          // 34304

// 16 MB scratch: W2 pre-rounded to tf32 (rna) so the mainloop has ZERO cvt for B
__device__ float4 g_W2r[(size_t)K * O / 4];

// ---------------- helpers ----------------
__device__ __forceinline__ uint32_t smem_u32(const void* p) {
    uint32_t a;
    asm("{ .reg .u64 t; cvta.to.shared.u64 t, %1; cvt.u32.u64 %0, t; }" : "=r"(a) : "l"(p));
    return a;
}

__device__ __forceinline__ uint32_t tf32u(float a) {
    uint32_t d;
    asm("cvt.rna.tf32.f32 %0, %1;" : "=r"(d) : "f"(a));
    return d;
}
__device__ __forceinline__ float to_tf32(float a) { return __uint_as_float(tf32u(a)); }

// elu with tf32 rounding (operand for the tf32 MMA)
__device__ __forceinline__ float elu_tf32(float z) {
    float zm = fminf(z, 0.0f);
    float zp = fmaxf(z, 0.0f);
    float e  = __expf(zm);           // z>0 -> e=1
    return to_tf32(e + (zp - 1.0f)); // z>0 -> z ; z<=0 -> exp(z)-1
}

// m16n8k8 tf32 mma.sync (sm_80-era; assembles on .target sm_103 — no 'a' feature)
__device__ __forceinline__ void mma8(float* c, const float4 a, uint32_t b0, uint32_t b1) {
    asm volatile(
        "mma.sync.aligned.m16n8k8.row.col.f32.tf32.tf32.f32 "
        "{%0,%1,%2,%3},{%4,%5,%6,%7},{%8,%9},{%0,%1,%2,%3};"
        : "+f"(c[0]), "+f"(c[1]), "+f"(c[2]), "+f"(c[3])
        : "r"(__float_as_uint(a.x)), "r"(__float_as_uint(a.y)),
          "r"(__float_as_uint(a.z)), "r"(__float_as_uint(a.w)),
          "r"(b0), "r"(b1));
}

// ---------------- prologue: round W2 to tf32 once ----------------
__global__ void w2_round_kernel(const float4* __restrict__ W2) {
    size_t i = (size_t)blockIdx.x * blockDim.x + threadIdx.x;   // over K*O/4
    float4 v = W2[i];
    v.x = to_tf32(v.x); v.y = to_tf32(v.y); v.z = to_tf32(v.z); v.w = to_tf32(v.w);
    g_W2r[i] = v;
}

// ---------------- main kernel ----------------
__global__ void __launch_bounds__(THREADS, 2)
mlp_gemm_kernel(const float* __restrict__ x, const float* __restrict__ W1,
                const float* __restrict__ b1, const float* __restrict__ b2,
                float* __restrict__ out)
{
    extern __shared__ float sm[];
    const uint32_t smu = smem_u32(sm);
    const int tid = threadIdx.x;
    const int wid = tid >> 5, lid = tid & 31;
    const int tg  = lid >> 2, tq = lid & 3;   // fragment geometry (B side)
    const int wm  = wid & 3,  wn = wid >> 2;  // warp grid 4x2
    const int m0  = blockIdx.x * MT;
    const int n0  = blockIdx.y * NT;

    // bsum[c] = sum_f b2[f, n0+c]
    if (tid < NT) {
        float s = 0.0f;
        #pragma unroll 8
        for (int f = 0; f < F; f++) s += b2[(size_t)f * O + n0 + tid];
        sm[BSUM + tid] = s;
    }

    float acc[2][8][4];
    #pragma unroll
    for (int mb = 0; mb < 2; mb++)
        #pragma unroll
        for (int nb = 0; nb < 8; nb++)
            #pragma unroll
            for (int i = 0; i < 4; i++) acc[mb][nb][i] = 0.0f;

    // producer thread mapping (A): thread covers rows ar, ar+64; k-quad ac
    const int ac = tid & 3;        // k cols ac*4 .. ac*4+3 within the 16-wide stage
    const int ar = tid >> 2;       // rows ar, ar+64
    // permuted-store constants for this thread:
    //   kq = ac*4 + j  ->  bk = ac>>1, kq' = kq&7, slot += 2*(ac&1), lane j-part = j
    const int a_bk   = ac >> 1;
    const int a_s2   = (ac & 1) * 2;

    // ---- stage producers ----
    auto produceB = [&](int s, int buf) {
        const int k0 = s * KB;
        int e = tid;
        #pragma unroll
        for (int i = 0; i < 2; i++, e += THREADS) {
            int k = e >> 5, nq = e & 31;                 // 16B chunk
            uint32_t dst = smu + (uint32_t)(BBS + buf * BS_SZ + k * BS_STRIDE + nq * 4) * 4u;
            const float* src = (const float*)g_W2r + (size_t)(k0 + k) * O + n0 + nq * 4;
            asm volatile("cp.async.cg.shared.global [%0], [%1], 16;\n"
                         :: "r"(dst), "l"(src) : "memory");
        }
    };
    auto produceA = [&](int s, int buf) {
        const int f  = s >> 3;
        const int h0 = (s & 7) << 4;
        const float4 w4 = *(const float4*)(W1 + (size_t)f * H + h0 + ac * 4);
        const float4 c4 = *(const float4*)(b1 + (size_t)f * H + h0 + ac * 4);
        #pragma unroll
        for (int i = 0; i < 2; i++) {
            const int r  = ar + i * 64;
            const float xv = __ldg(x + (size_t)(m0 + r) * F + f);   // L1-resident
            float av[4];
            av[0] = elu_tf32(fmaf(xv, w4.x, c4.x));
            av[1] = elu_tf32(fmaf(xv, w4.y, c4.y));
            av[2] = elu_tf32(fmaf(xv, w4.z, c4.z));
            av[3] = elu_tf32(fmaf(xv, w4.w, c4.w));
            const int bm    = r >> 4;
            const int rr    = r & 15;
            const int slot  = (rr >> 3) + a_s2;
            const int lane0 = (rr & 7) * 4;
            float* dst = &sm[AS + buf * AS_SZ + ((a_bk * 8 + bm) * 32 + lane0) * 4 + slot];
            #pragma unroll
            for (int j = 0; j < 4; j++) dst[j * 4] = av[j];
        }
    };

    // prologue: stage 0
    produceB(0, 0);
    asm volatile("cp.async.commit_group;\n" ::: "memory");
    produceA(0, 0);

    #pragma unroll 1
    for (int s = 0; s < NSTAGES; s++) {
        const int buf = s & 1;
        asm volatile("cp.async.wait_group 0;\n" ::: "memory");
        __syncthreads();   // stage-s B & A visible; buf^1 free for reuse

        if (s + 1 < NSTAGES) {
            produceB(s + 1, buf ^ 1);
            asm volatile("cp.async.commit_group;\n" ::: "memory");
            produceA(s + 1, buf ^ 1);
        }

        // ---- consume stage s: 2 k8-steps x (2 m16) x (8 n8) mmas ----
        const float* As = sm + AS + buf * AS_SZ;
        const float* Bs = sm + BBS + buf * BS_SZ;
        #pragma unroll
        for (int bk = 0; bk < 2; bk++) {
            // A fragments: one LDS.128 each (fragment-permuted layout)
            float4 a0 = *(const float4*)&As[((bk * 8 + wm * 2 + 0) * 32 + lid) * 4];
            float4 a1 = *(const float4*)&As[((bk * 8 + wm * 2 + 1) * 32 + lid) * 4];
            const float* bbase = Bs + (bk * 8 + tq) * BS_STRIDE + wn * 64 + tg;
            #pragma unroll
            for (int nb = 0; nb < 8; nb++) {
                uint32_t b0 = __float_as_uint(bbase[nb * 8]);                   // pre-rounded
                uint32_t b1r = __float_as_uint(bbase[4 * BS_STRIDE + nb * 8]);
                mma8(acc[0][nb], a0, b0, b1r);
                mma8(acc[1][nb], a1, b0, b1r);
            }
        }
    }

    // ---- epilogue: add summed bias, scale by 1/sqrt(F)=0.125, store ----
    #pragma unroll
    for (int mb = 0; mb < 2; mb++) {
        const int row = m0 + wm * 32 + mb * 16 + tg;
        #pragma unroll
        for (int nb = 0; nb < 8; nb++) {
            const int cl = wn * 64 + nb * 8 + tq * 2;   // local col
            const float bs0 = sm[BSUM + cl];
            const float bs1 = sm[BSUM + cl + 1];
            float2 v0, v1;
            v0.x = (acc[mb][nb][0] + bs0) * 0.125f;
            v0.y = (acc[mb][nb][1] + bs1) * 0.125f;
            v1.x = (acc[mb][nb][2] + bs0) * 0.125f;
            v1.y = (acc[mb][nb][3] + bs1) * 0.125f;
            *(float2*)(out + (size_t)row * O + n0 + cl)       = v0;
            *(float2*)(out + (size_t)(row + 8) * O + n0 + cl) = v1;
        }
    }
}

// ---------------- launch ----------------
extern "C" void kernel_launch(void* const* d_in, const int* in_sizes, int n_in,
                              void* d_out, int out_size) {
    const float* x  = (const float*)d_in[0];   // [16384, 64]
    const float* W1 = (const float*)d_in[1];   // [64, 128]
    const float* b1 = (const float*)d_in[2];   // [64, 128]
    const float* W2 = (const float*)d_in[3];   // [64, 128, 512] == [K, O]
    const float* b2 = (const float*)d_in[4];   // [64, 512]
    float* out = (float*)d_out;                // [16384, 512]

    cudaFuncSetAttribute(mlp_gemm_kernel,
                         cudaFuncAttributeMaxDynamicSharedMemorySize, SMEM_BYTES);

    w2_round_kernel<<<(K * O / 4) / 256, 256>>>((const float4*)W2);
    dim3 grid(16384 / MT, O / NT);             // 128 x 4
    mlp_gemm_kernel<<<grid, THREADS, SMEM_BYTES>>>(x, W1, b1, b2, out);
}

// round 17
// speedup vs baseline: 1.5826x; 1.5826x over previous
#include <cuda_runtime.h>
#include <cstdint>

// ---------------- problem constants ----------------
constexpr int F = 64;
constexpr int H = 128;
constexpr int O = 512;
constexpr int K = F * H;            // 8192
constexpr int MT = 128;             // CTA M tile
constexpr int NT = 128;             // CTA N tile
constexpr int KB = 16;              // K per pipeline stage
constexpr int NSTAGES = K / KB;     // 512
constexpr int THREADS = 256;        // 8 warps: 4 (m) x 2 (n), warp tile 32x64

// ---------------- smem layout (float offsets) ----------------
// A FRAGMENT-PERMUTED: [buf][blk(16)=bk*8+bm][lane(32)][slot(4)]
//   slot0=(tg,  k=tq) slot1=(tg+8,tq) slot2=(tg,tq+4) slot3=(tg+8,tq+4)
// consumer A fragment = ONE LDS.128; producer lane = ONE STS.128.
constexpr int XS        = 0;                          // x tile [F][129]
constexpr int XS_STRIDE = 129;
constexpr int BSUM      = XS + F * XS_STRIDE;         // 8256
constexpr int AS        = BSUM + 128;                 // 8384, 2 bufs x 2048
constexpr int AS_SZ     = 2048;                       // 16*32*4
constexpr int BBS       = AS + 2 * AS_SZ;             // 12480
constexpr int BS_STRIDE = 136;                        // 128 + 8 pad
constexpr int BS_SZ     = KB * BS_STRIDE;             // 2176
constexpr int SMEM_FLOATS = BBS + 2 * BS_SZ;          // 16832
constexpr int SMEM_BYTES  = SMEM_FLOATS * 4;          // 67328 (2 CTAs/SM ok)

// scratch: W2 pre-rounded to tf32 (zero cvt in mainloop); W1/b1 interleaved
__device__ float4 g_W2r[(size_t)K * O / 4];
__device__ float2 g_W1b1[(size_t)F * H];

// ---------------- helpers ----------------
__device__ __forceinline__ uint32_t smem_u32(const void* p) {
    uint32_t a;
    asm("{ .reg .u64 t; cvta.to.shared.u64 t, %1; cvt.u32.u64 %0, t; }" : "=r"(a) : "l"(p));
    return a;
}
__device__ __forceinline__ uint32_t tf32u(float a) {
    uint32_t d;
    asm("cvt.rna.tf32.f32 %0, %1;" : "=r"(d) : "f"(a));
    return d;
}
__device__ __forceinline__ float to_tf32(float a) { return __uint_as_float(tf32u(a)); }

// elu with tf32 rounding (A operand for the tf32 MMA)
__device__ __forceinline__ float elu_tf32(float z) {
    float zm = fminf(z, 0.0f);
    float zp = fmaxf(z, 0.0f);
    float e  = __expf(zm);           // z>0 -> 1
    return to_tf32(e + (zp - 1.0f)); // z>0 -> z ; z<=0 -> exp(z)-1
}

// m16n8k8 tf32 mma.sync (sm_80-era; assembles on .target sm_103)
__device__ __forceinline__ void mma8(float* c, const float4 a, float b0, float b1) {
    asm volatile(
        "mma.sync.aligned.m16n8k8.row.col.f32.tf32.tf32.f32 "
        "{%0,%1,%2,%3},{%4,%5,%6,%7},{%8,%9},{%0,%1,%2,%3};"
        : "+f"(c[0]), "+f"(c[1]), "+f"(c[2]), "+f"(c[3])
        : "r"(__float_as_uint(a.x)), "r"(__float_as_uint(a.y)),
          "r"(__float_as_uint(a.z)), "r"(__float_as_uint(a.w)),
          "r"(__float_as_uint(b0)), "r"(__float_as_uint(b1)));
}

// ---------------- prologue kernels ----------------
__global__ void w2_round_kernel(const float4* __restrict__ W2) {
    size_t i = (size_t)blockIdx.x * blockDim.x + threadIdx.x;   // over K*O/4
    float4 v = W2[i];
    v.x = to_tf32(v.x); v.y = to_tf32(v.y); v.z = to_tf32(v.z); v.w = to_tf32(v.w);
    g_W2r[i] = v;
}
__global__ void w1b1_pack_kernel(const float* __restrict__ W1, const float* __restrict__ b1) {
    int i = blockIdx.x * blockDim.x + threadIdx.x;              // over F*H
    g_W1b1[i] = make_float2(W1[i], b1[i]);
}

// ---------------- main kernel ----------------
__global__ void __launch_bounds__(THREADS, 2)
mlp_gemm_kernel(const float* __restrict__ x, const float* __restrict__ b2,
                float* __restrict__ out)
{
    extern __shared__ float sm[];
    const uint32_t smu = smem_u32(sm);
    const int tid = threadIdx.x;
    const int wid = tid >> 5, lid = tid & 31;
    const int tg  = lid >> 2, tq = lid & 3;   // fragment geometry
    const int wm  = wid & 3,  wn = wid >> 2;  // warp grid 4x2
    const int m0  = blockIdx.x * MT;
    const int n0  = blockIdx.y * NT;

    // x tile: xs[f][r] = x[m0+r, f]
    for (int idx = tid; idx < MT * F; idx += THREADS) {
        int r = idx >> 6, f = idx & 63;
        sm[XS + f * XS_STRIDE + r] = x[(size_t)(m0 + r) * F + f];
    }
    // bsum[c] = sum_f b2[f, n0+c]
    if (tid < NT) {
        float s = 0.0f;
        #pragma unroll 8
        for (int f = 0; f < F; f++) s += b2[(size_t)f * O + n0 + tid];
        sm[BSUM + tid] = s;
    }
    __syncthreads();   // *** R17 fix: x tile must be fully visible before produceA(0,0)
                       //     (R16's 2.9e-3 failure = stage-0 cross-warp RAW race on XS)

    float acc[2][8][4];
    #pragma unroll
    for (int mb = 0; mb < 2; mb++)
        #pragma unroll
        for (int nb = 0; nb < 8; nb++)
            #pragma unroll
            for (int i = 0; i < 4; i++) acc[mb][nb][i] = 0.0f;

    // producer A rows for this thread (warp wid owns m16-block bm = wid)
    const int ar0 = wid * 16 + tg;            // and ar0 + 8

    auto produceB = [&](int s, int buf) {
        const int k0 = s * KB;
        int e = tid;
        #pragma unroll
        for (int i = 0; i < 2; i++, e += THREADS) {
            int k = e >> 5, nq = e & 31;                 // 16B chunk
            uint32_t dst = smu + (uint32_t)(BBS + buf * BS_SZ + k * BS_STRIDE + nq * 4) * 4u;
            const float* src = (const float*)g_W2r + (size_t)(k0 + k) * O + n0 + nq * 4;
            asm volatile("cp.async.cg.shared.global [%0], [%1], 16;\n"
                         :: "r"(dst), "l"(src) : "memory");
        }
    };
    auto produceA = [&](int s, int buf) {
        const int f  = s >> 3;
        const int h0 = (s & 7) << 4;
        const float x0 = sm[XS + f * XS_STRIDE + ar0];
        const float x1 = sm[XS + f * XS_STRIDE + ar0 + 8];
        #pragma unroll
        for (int bk = 0; bk < 2; bk++) {
            const int hb = h0 + bk * 8 + tq;
            const float2 wc0 = __ldg(&g_W1b1[(size_t)f * H + hb]);      // k = bk*8+tq
            const float2 wc1 = __ldg(&g_W1b1[(size_t)f * H + hb + 4]);  // k+4
            float4 av;
            av.x = elu_tf32(fmaf(x0, wc0.x, wc0.y));   // (tg,   k)
            av.y = elu_tf32(fmaf(x1, wc0.x, wc0.y));   // (tg+8, k)
            av.z = elu_tf32(fmaf(x0, wc1.x, wc1.y));   // (tg,   k+4)
            av.w = elu_tf32(fmaf(x1, wc1.x, wc1.y));   // (tg+8, k+4)
            *(float4*)&sm[AS + buf * AS_SZ + ((bk * 8 + wid) * 32 + lid) * 4] = av;
        }
    };

    // prologue: stage 0
    produceB(0, 0);
    asm volatile("cp.async.commit_group;\n" ::: "memory");
    produceA(0, 0);

    #pragma unroll 1
    for (int s = 0; s < NSTAGES; s++) {
        const int buf = s & 1;
        asm volatile("cp.async.wait_group 0;\n" ::: "memory");
        __syncthreads();   // stage-s visible; buf^1 free

        if (s + 1 < NSTAGES) {
            produceB(s + 1, buf ^ 1);
            asm volatile("cp.async.commit_group;\n" ::: "memory");
            produceA(s + 1, buf ^ 1);
        }

        const float* As = sm + AS + buf * AS_SZ;
        const float* Bs = sm + BBS + buf * BS_SZ;
        #pragma unroll
        for (int bk = 0; bk < 2; bk++) {
            // A fragments: one LDS.128 each
            float4 a0 = *(const float4*)&As[((bk * 8 + wm * 2 + 0) * 32 + lid) * 4];
            float4 a1 = *(const float4*)&As[((bk * 8 + wm * 2 + 1) * 32 + lid) * 4];
            // B: rows bk*8+tq (b0) and +4 (b1); permuted cols q*32 + tg*4 + i
            const float* bp = Bs + (bk * 8 + tq) * BS_STRIDE + wn * 64 + tg * 4;
            #pragma unroll
            for (int q = 0; q < 2; q++) {
                float4 bl = *(const float4*)(bp + q * 32);                  // b0 x4 nb
                float4 bh = *(const float4*)(bp + q * 32 + 4 * BS_STRIDE);  // b1 x4 nb
                mma8(acc[0][q * 4 + 0], a0, bl.x, bh.x);
                mma8(acc[1][q * 4 + 0], a1, bl.x, bh.x);
                mma8(acc[0][q * 4 + 1], a0, bl.y, bh.y);
                mma8(acc[1][q * 4 + 1], a1, bl.y, bh.y);
                mma8(acc[0][q * 4 + 2], a0, bl.z, bh.z);
                mma8(acc[1][q * 4 + 2], a1, bl.z, bh.z);
                mma8(acc[0][q * 4 + 3], a0, bl.w, bh.w);
                mma8(acc[1][q * 4 + 3], a1, bl.w, bh.w);
            }
        }
    }

    // ---- epilogue ----
    // fragment n-slot j of tile nb=q*4+i maps to physical col q*32 + j*4 + i.
    // c0/c1 are n-slots tq*2, tq*2+1 -> phys cols q*32 + tq*8 + i (+4 for c1).
    #pragma unroll
    for (int mb = 0; mb < 2; mb++) {
        #pragma unroll
        for (int h = 0; h < 2; h++) {           // row half: c0c1 vs c2c3
            const int row = m0 + wm * 32 + mb * 16 + tg + h * 8;
            float* orow = out + (size_t)row * O + n0 + wn * 64;
            #pragma unroll
            for (int q = 0; q < 2; q++) {
                const int cb = q * 32 + tq * 8;
                float4 bs0 = *(const float4*)&sm[BSUM + wn * 64 + cb];
                float4 bs1 = *(const float4*)&sm[BSUM + wn * 64 + cb + 4];
                float4 v0, v1;
                v0.x = (acc[mb][q * 4 + 0][h * 2]     + bs0.x) * 0.125f;
                v0.y = (acc[mb][q * 4 + 1][h * 2]     + bs0.y) * 0.125f;
                v0.z = (acc[mb][q * 4 + 2][h * 2]     + bs0.z) * 0.125f;
                v0.w = (acc[mb][q * 4 + 3][h * 2]     + bs0.w) * 0.125f;
                v1.x = (acc[mb][q * 4 + 0][h * 2 + 1] + bs1.x) * 0.125f;
                v1.y = (acc[mb][q * 4 + 1][h * 2 + 1] + bs1.y) * 0.125f;
                v1.z = (acc[mb][q * 4 + 2][h * 2 + 1] + bs1.z) * 0.125f;
                v1.w = (acc[mb][q * 4 + 3][h * 2 + 1] + bs1.w) * 0.125f;
                *(float4*)(orow + cb)     = v0;
                *(float4*)(orow + cb + 4) = v1;
            }
        }
    }
}

// ---------------- launch ----------------
extern "C" void kernel_launch(void* const* d_in, const int* in_sizes, int n_in,
                              void* d_out, int out_size) {
    const float* x  = (const float*)d_in[0];   // [16384, 64]
    const float* W1 = (const float*)d_in[1];   // [64, 128]
    const float* b1 = (const float*)d_in[2];   // [64, 128]
    const float* W2 = (const float*)d_in[3];   // [64, 128, 512] == [K, O]
    const float* b2 = (const float*)d_in[4];   // [64, 512]
    float* out = (float*)d_out;                // [16384, 512]

    cudaFuncSetAttribute(mlp_gemm_kernel,
                         cudaFuncAttributeMaxDynamicSharedMemorySize, SMEM_BYTES);

    w2_round_kernel<<<(K * O / 4) / 256, 256>>>((const float4*)W2);
    w1b1_pack_kernel<<<(F * H) / 256, 256>>>(W1, b1);
    dim3 grid(16384 / MT, O / NT);             // 128 x 4
    mlp_gemm_kernel<<<grid, THREADS, SMEM_BYTES>>>(x, b2, out);
}